// round 3
// baseline (speedup 1.0000x reference)
#include <cuda_runtime.h>
#include <cuda_bf16.h>

#define CIN 192
#define COUT 192
#define IMG_H 256
#define IMG_W 256
#define NB 4

// Scratch (device globals: the sanctioned no-alloc workaround)
__device__ __align__(16) __nv_bfloat16 g_xhi[NB * CIN * IMG_H * IMG_W];
__device__ __align__(16) __nv_bfloat16 g_xlo[NB * CIN * IMG_H * IMG_W];
__device__ __align__(16) __nv_bfloat16 g_whi[9 * COUT * CIN];
__device__ __align__(16) __nv_bfloat16 g_wlo[9 * COUT * CIN];
__device__ __align__(16) float g_valid[NB * IMG_H * IMG_W];

// ---------------------------------------------------------------------------
// Pass 1a: fp32 x -> bf16 hi/lo split planes
// ---------------------------------------------------------------------------
__global__ void cvt_x_kernel(const float* __restrict__ x) {
    int i = (blockIdx.x * blockDim.x + threadIdx.x) * 4;
    float4 f = *(const float4*)(x + i);
    __nv_bfloat16 h0 = __float2bfloat16(f.x);
    __nv_bfloat16 h1 = __float2bfloat16(f.y);
    __nv_bfloat16 h2 = __float2bfloat16(f.z);
    __nv_bfloat16 h3 = __float2bfloat16(f.w);
    __nv_bfloat16 l0 = __float2bfloat16(f.x - __bfloat162float(h0));
    __nv_bfloat16 l1 = __float2bfloat16(f.y - __bfloat162float(h1));
    __nv_bfloat16 l2 = __float2bfloat16(f.z - __bfloat162float(h2));
    __nv_bfloat16 l3 = __float2bfloat16(f.w - __bfloat162float(h3));
    __nv_bfloat162* dh = (__nv_bfloat162*)(g_xhi + i);
    __nv_bfloat162* dl = (__nv_bfloat162*)(g_xlo + i);
    dh[0] = __nv_bfloat162(h0, h1);
    dh[1] = __nv_bfloat162(h2, h3);
    dl[0] = __nv_bfloat162(l0, l1);
    dl[1] = __nv_bfloat162(l2, l3);
}

// ---------------------------------------------------------------------------
// Pass 1b: weight [cout][cin][kh][kw] -> tap-major [tap][cout][cin] hi/lo
// ---------------------------------------------------------------------------
__global__ void cvt_w_kernel(const float* __restrict__ w) {
    int i = blockIdx.x * blockDim.x + threadIdx.x;
    if (i >= COUT * CIN * 9) return;
    int kw = i % 3;
    int kh = (i / 3) % 3;
    int ci = (i / 9) % CIN;
    int co = i / (9 * CIN);
    float v = w[i];
    __nv_bfloat16 hi = __float2bfloat16(v);
    __nv_bfloat16 lo = __float2bfloat16(v - __bfloat162float(hi));
    int tap = kh * 3 + kw;
    int dst = (tap * COUT + co) * CIN + ci;
    g_whi[dst] = hi;
    g_wlo[dst] = lo;
}

// ---------------------------------------------------------------------------
// Pass 1c: validity = 3x3 "any mask != 0" pool
// ---------------------------------------------------------------------------
__global__ void valid_kernel(const int* __restrict__ mask) {
    int i = blockIdx.x * blockDim.x + threadIdx.x;
    if (i >= NB * IMG_H * IMG_W) return;
    int b = i >> 16;
    int y = (i >> 8) & 255;
    int x = i & 255;
    const int* mb = mask + (b << 16);
    int v = 0;
#pragma unroll
    for (int dy = -1; dy <= 1; ++dy) {
        int yy = y + dy;
        if (yy < 0 || yy > 255) continue;
#pragma unroll
        for (int dx = -1; dx <= 1; ++dx) {
            int xx = x + dx;
            if (xx < 0 || xx > 255) continue;
            v |= mb[yy * 256 + xx];
        }
    }
    g_valid[i] = (v != 0) ? 1.0f : 0.0f;
}

// ---------------------------------------------------------------------------
// Pass 2: implicit-GEMM conv. CTA = 64 cout x 128 pixels (one row segment).
// 4 warps along pixels (32 each). mma.sync m16n8k16 bf16 -> f32.
// 3 split products: Whi*Xhi + Whi*Xlo + Wlo*Xhi.
// ---------------------------------------------------------------------------
#define XSTRIDE 18                 // halves per pixel slot (16 cin + 2 pad)
#define XS_HALVES (3 * 130 * XSTRIDE)
#define WS_HALVES (9 * 64 * 16)
#define SMEM_BYTES (2 * XS_HALVES * 2 + 2 * WS_HALVES * 2 + 128 * 4)

__device__ __forceinline__ void mma_bf16(float* d, const unsigned* a,
                                         unsigned b0, unsigned b1) {
    asm volatile(
        "mma.sync.aligned.m16n8k16.row.col.f32.bf16.bf16.f32 "
        "{%0,%1,%2,%3}, {%4,%5,%6,%7}, {%8,%9}, {%0,%1,%2,%3};\n"
        : "+f"(d[0]), "+f"(d[1]), "+f"(d[2]), "+f"(d[3])
        : "r"(a[0]), "r"(a[1]), "r"(a[2]), "r"(a[3]), "r"(b0), "r"(b1));
}

__global__ void __launch_bounds__(128) conv_kernel(const float* __restrict__ bias,
                                                   float* __restrict__ out) {
    extern __shared__ unsigned char smem_raw[];
    __nv_bfloat16* XsH = (__nv_bfloat16*)smem_raw;             // [3][130][18]
    __nv_bfloat16* XsL = XsH + XS_HALVES;
    __nv_bfloat16* WsH = XsL + XS_HALVES;                      // [9][64][16]
    __nv_bfloat16* WsL = WsH + WS_HALVES;
    float* Vs = (float*)(WsL + WS_HALVES);                     // [128]
    unsigned short* XsHu = (unsigned short*)XsH;
    unsigned short* XsLu = (unsigned short*)XsL;

    const int tid = threadIdx.x;
    const int warp = tid >> 5;
    const int lane = tid & 31;
    const int g = lane >> 2;     // group id (0..7)
    const int t = lane & 3;      // thread-in-group (0..3)

    const int tile = blockIdx.x;             // 0..2047
    const int w0 = (tile & 1) << 7;          // 0 or 128
    const int h = (tile >> 1) & 255;
    const int b = tile >> 9;
    const int cout0 = blockIdx.y << 6;       // 0, 64, 128

    // pooled validity for this pixel tile
    Vs[tid] = g_valid[((b << 8) + h) * 256 + w0 + tid];

    float acc[4][4][4];
#pragma unroll
    for (int mf = 0; mf < 4; ++mf)
#pragma unroll
        for (int nf = 0; nf < 4; ++nf)
#pragma unroll
            for (int i = 0; i < 4; ++i) acc[mf][nf][i] = 0.0f;

    for (int cc = 0; cc < 12; ++cc) {           // cin chunks of 16
        __syncthreads();
        // --- stage weights: all 9 taps, 64 cout x 16 cin, hi+lo ---
        for (int r = tid; r < 576; r += 128) {
            int tap = r >> 6;
            int m = r & 63;
            int src = (tap * COUT + cout0 + m) * CIN + cc * 16;
            const uint4* sh = (const uint4*)(g_whi + src);
            const uint4* sl = (const uint4*)(g_wlo + src);
            uint4* dh = (uint4*)(WsH + r * 16);
            uint4* dl = (uint4*)(WsL + r * 16);
            dh[0] = sh[0]; dh[1] = sh[1];
            dl[0] = sl[0]; dl[1] = sl[1];
        }
        // --- stage X halo: 16 cin x 3 rows x 130 pixels, hi+lo ---
        for (int idx = tid; idx < 48 * 66; idx += 128) {
            int rowid = idx / 66;
            int u = idx - rowid * 66;
            int k = rowid / 3;
            int rr = rowid - k * 3;
            int hh = h - 1 + rr;
            int gwp = w0 - 2 + (u << 1);       // even global w of the pair
            unsigned vh = 0, vl = 0;
            if ((unsigned)hh < 256u && (unsigned)gwp <= 254u) {
                int gi = ((b * CIN + cc * 16 + k) * 256 + hh) * 256 + gwp;
                vh = *(const unsigned*)(g_xhi + gi);
                vl = *(const unsigned*)(g_xlo + gi);
            }
            int sp = gwp - w0 + 1;             // smem pixel index of half 0
            int sbase = (rr * 130) * XSTRIDE + k;
            if ((unsigned)sp <= 129u) {
                XsHu[sbase + sp * XSTRIDE] = (unsigned short)vh;
                XsLu[sbase + sp * XSTRIDE] = (unsigned short)vl;
            }
            int sp1 = sp + 1;
            if ((unsigned)sp1 <= 129u) {
                XsHu[sbase + sp1 * XSTRIDE] = (unsigned short)(vh >> 16);
                XsLu[sbase + sp1 * XSTRIDE] = (unsigned short)(vl >> 16);
            }
        }
        __syncthreads();

        // --- compute: 9 taps x (Ahi*Bhi + Ahi*Blo + Alo*Bhi) ---
#pragma unroll
        for (int tap = 0; tap < 9; ++tap) {
            const int kh = tap / 3;
            const int kw = tap - kh * 3;
            unsigned A[4][4];
            // A_hi fragments (64x16 tile of this tap)
#pragma unroll
            for (int mf = 0; mf < 4; ++mf) {
                int base = (tap * 64 + mf * 16 + g) * 16 + 2 * t;
                A[mf][0] = *(const unsigned*)(WsH + base);
                A[mf][1] = *(const unsigned*)(WsH + base + 128);
                A[mf][2] = *(const unsigned*)(WsH + base + 8);
                A[mf][3] = *(const unsigned*)(WsH + base + 136);
            }
#pragma unroll
            for (int nf = 0; nf < 4; ++nf) {
                int sp = (warp << 5) + (nf << 3) + g + kw;
                int xb = (kh * 130 + sp) * XSTRIDE + 2 * t;
                unsigned b0 = *(const unsigned*)(XsH + xb);
                unsigned b1 = *(const unsigned*)(XsH + xb + 8);
                unsigned c0 = *(const unsigned*)(XsL + xb);
                unsigned c1 = *(const unsigned*)(XsL + xb + 8);
#pragma unroll
                for (int mf = 0; mf < 4; ++mf) mma_bf16(acc[mf][nf], A[mf], b0, b1);
#pragma unroll
                for (int mf = 0; mf < 4; ++mf) mma_bf16(acc[mf][nf], A[mf], c0, c1);
            }
            // A_lo fragments, times X_hi
#pragma unroll
            for (int mf = 0; mf < 4; ++mf) {
                int base = (tap * 64 + mf * 16 + g) * 16 + 2 * t;
                A[mf][0] = *(const unsigned*)(WsL + base);
                A[mf][1] = *(const unsigned*)(WsL + base + 128);
                A[mf][2] = *(const unsigned*)(WsL + base + 8);
                A[mf][3] = *(const unsigned*)(WsL + base + 136);
            }
#pragma unroll
            for (int nf = 0; nf < 4; ++nf) {
                int sp = (warp << 5) + (nf << 3) + g + kw;
                int xb = (kh * 130 + sp) * XSTRIDE + 2 * t;
                unsigned b0 = *(const unsigned*)(XsH + xb);
                unsigned b1 = *(const unsigned*)(XsH + xb + 8);
#pragma unroll
                for (int mf = 0; mf < 4; ++mf) mma_bf16(acc[mf][nf], A[mf], b0, b1);
            }
        }
    }

    // --- epilogue: +bias, * validity, store fp32 ---
#pragma unroll
    for (int mf = 0; mf < 4; ++mf) {
        int m0 = cout0 + mf * 16 + g;
        float bz0 = bias[m0];
        float bz1 = bias[m0 + 8];
#pragma unroll
        for (int nf = 0; nf < 4; ++nf) {
            int n = (warp << 5) + (nf << 3) + 2 * t;
            float v0 = Vs[n];
            float v1 = Vs[n + 1];
            int o = ((b * COUT + m0) * 256 + h) * 256 + w0 + n;
            float2 r0;
            r0.x = (acc[mf][nf][0] + bz0) * v0;
            r0.y = (acc[mf][nf][1] + bz0) * v1;
            *(float2*)(out + o) = r0;
            float2 r1;
            r1.x = (acc[mf][nf][2] + bz1) * v0;
            r1.y = (acc[mf][nf][3] + bz1) * v1;
            *(float2*)(out + o + 8 * 65536) = r1;
        }
    }
}

// ---------------------------------------------------------------------------
extern "C" void kernel_launch(void* const* d_in, const int* in_sizes, int n_in,
                              void* d_out, int out_size) {
    const float* x = (const float*)d_in[0];
    const int* mask = (const int*)d_in[1];
    const float* w = (const float*)d_in[2];
    const float* bias = (const float*)d_in[3];
    float* out = (float*)d_out;

    cudaFuncSetAttribute(conv_kernel, cudaFuncAttributeMaxDynamicSharedMemorySize,
                         SMEM_BYTES);

    cvt_x_kernel<<<(NB * CIN * IMG_H * IMG_W) / 4 / 256, 256>>>(x);
    cvt_w_kernel<<<(COUT * CIN * 9 + 255) / 256, 256>>>(w);
    valid_kernel<<<(NB * IMG_H * IMG_W + 255) / 256, 256>>>(mask);

    dim3 grid(2048, 3, 1);
    conv_kernel<<<grid, 128, SMEM_BYTES>>>(bias, out);
}

// round 4
// speedup vs baseline: 1.8211x; 1.8211x over previous
#include <cuda_runtime.h>
#include <cuda_bf16.h>

#define CIN 192
#define COUT 192
#define NB 4

// Scratch (device globals: the sanctioned no-alloc workaround)
// X is stored PIXEL-MAJOR: [b][h][w][cin]
__device__ __align__(256) __nv_bfloat16 g_xhi[NB * 256 * 256 * CIN];
__device__ __align__(256) __nv_bfloat16 g_xlo[NB * 256 * 256 * CIN];
__device__ __align__(256) __nv_bfloat16 g_whi[9 * COUT * CIN];   // [tap][cout][cin]
__device__ __align__(256) __nv_bfloat16 g_wlo[9 * COUT * CIN];
__device__ __align__(256) float g_valid[NB * 256 * 256];

// ---------------------------------------------------------------------------
// Pass 1a: fp32 x [b][cin][h][w] -> bf16 hi/lo, pixel-major [b][h][w][cin]
// Block: 64 pixels (one row segment) x all 192 cin, transposed through smem.
// ---------------------------------------------------------------------------
#define TP_STRIDE 200   // halves per pixel row in smem (192 + 8 pad)
__global__ void __launch_bounds__(256) cvt_x_kernel(const float* __restrict__ x) {
    __shared__ __nv_bfloat16 sH[64 * TP_STRIDE];
    __shared__ __nv_bfloat16 sL[64 * TP_STRIDE];
    const int tid = threadIdx.x;
    const int w0 = blockIdx.x << 6;
    const int h = blockIdx.y;
    const int b = blockIdx.z;
    const int wloc = tid & 63;
    const int cg = tid >> 6;

    const float* xb = x + ((b * CIN) * 256 + h) * 256 + w0;
    for (int ci = cg; ci < CIN; ci += 4) {
        float v = xb[ci * 65536 + wloc];
        __nv_bfloat16 hi = __float2bfloat16(v);
        __nv_bfloat16 lo = __float2bfloat16(v - __bfloat162float(hi));
        sH[wloc * TP_STRIDE + ci] = hi;
        sL[wloc * TP_STRIDE + ci] = lo;
    }
    __syncthreads();

    int pixbase = ((b * 256 + h) * 256 + w0) * CIN;
    uint4* dh = (uint4*)(g_xhi + pixbase);
    uint4* dl = (uint4*)(g_xlo + pixbase);
    for (int j = tid; j < 64 * 24; j += 256) {     // 24 uint4 per pixel
        int p = j / 24, c8 = j % 24;
        dh[j] = *(const uint4*)(sH + p * TP_STRIDE + c8 * 8);
        dl[j] = *(const uint4*)(sL + p * TP_STRIDE + c8 * 8);
    }
}

// ---------------------------------------------------------------------------
// Pass 1b: weight [cout][cin][kh][kw] -> tap-major [tap][cout][cin] hi/lo
// ---------------------------------------------------------------------------
__global__ void cvt_w_kernel(const float* __restrict__ w) {
    int i = blockIdx.x * blockDim.x + threadIdx.x;
    if (i >= COUT * CIN * 9) return;
    int kw = i % 3;
    int kh = (i / 3) % 3;
    int ci = (i / 9) % CIN;
    int co = i / (9 * CIN);
    float v = w[i];
    __nv_bfloat16 hi = __float2bfloat16(v);
    __nv_bfloat16 lo = __float2bfloat16(v - __bfloat162float(hi));
    int tap = kh * 3 + kw;
    int dst = (tap * COUT + co) * CIN + ci;
    g_whi[dst] = hi;
    g_wlo[dst] = lo;
}

// ---------------------------------------------------------------------------
// Pass 1c: validity = 3x3 "any mask != 0" pool
// ---------------------------------------------------------------------------
__global__ void valid_kernel(const int* __restrict__ mask) {
    int i = blockIdx.x * blockDim.x + threadIdx.x;
    if (i >= NB * 256 * 256) return;
    int b = i >> 16;
    int y = (i >> 8) & 255;
    int x = i & 255;
    const int* mb = mask + (b << 16);
    int v = 0;
#pragma unroll
    for (int dy = -1; dy <= 1; ++dy) {
        int yy = y + dy;
        if (yy < 0 || yy > 255) continue;
#pragma unroll
        for (int dx = -1; dx <= 1; ++dx) {
            int xx = x + dx;
            if (xx < 0 || xx > 255) continue;
            v |= mb[yy * 256 + xx];
        }
    }
    g_valid[i] = (v != 0) ? 1.0f : 0.0f;
}

// ---------------------------------------------------------------------------
// Pass 2: implicit-GEMM conv. CTA = 64 cout x 256 pixels (one full image row).
// 8 warps, 32 pixels each. ldmatrix + mma.sync m16n8k16 bf16 -> f32.
// 3 split products: Whi*Xhi + Whi*Xlo + Wlo*Xhi.
// ---------------------------------------------------------------------------
#define XROW (258 * 32)                 // bytes per kh-row of X halo
#define XS_BYTES (3 * XROW)             // 24768
#define WS_BYTES (9 * 64 * 32)          // 18432
#define SMEM_BYTES (2 * XS_BYTES + 2 * WS_BYTES + 256 * 4)

__device__ __forceinline__ unsigned sw(unsigned off) {
    return off ^ ((off & 128) >> 3);    // toggle 16B granule on bit7 -> conflict-free
}

#define LDSM4(r, addr)                                                        \
    asm volatile("ldmatrix.sync.aligned.m8n8.x4.shared.b16 {%0,%1,%2,%3}, [%4];" \
                 : "=r"((r)[0]), "=r"((r)[1]), "=r"((r)[2]), "=r"((r)[3])     \
                 : "r"(addr))
#define LDSM2(r0, r1, addr)                                                   \
    asm volatile("ldmatrix.sync.aligned.m8n8.x2.shared.b16 {%0,%1}, [%2];"    \
                 : "=r"(r0), "=r"(r1) : "r"(addr))
#define CP16(dst, src, n)                                                     \
    asm volatile("cp.async.cg.shared.global [%0], [%1], 16, %2;"              \
                 :: "r"(dst), "l"(src), "r"(n))

__device__ __forceinline__ void mma_bf16(float* d, const unsigned* a,
                                         unsigned b0, unsigned b1) {
    asm volatile(
        "mma.sync.aligned.m16n8k16.row.col.f32.bf16.bf16.f32 "
        "{%0,%1,%2,%3}, {%4,%5,%6,%7}, {%8,%9}, {%0,%1,%2,%3};\n"
        : "+f"(d[0]), "+f"(d[1]), "+f"(d[2]), "+f"(d[3])
        : "r"(a[0]), "r"(a[1]), "r"(a[2]), "r"(a[3]), "r"(b0), "r"(b1));
}

__global__ void __launch_bounds__(256, 2) conv_kernel(const float* __restrict__ bias,
                                                      float* __restrict__ out) {
    extern __shared__ unsigned char smem_raw[];
    const unsigned sbase = (unsigned)__cvta_generic_to_shared(smem_raw);
    const unsigned xh = sbase;
    const unsigned xl = xh + XS_BYTES;
    const unsigned wh = xl + XS_BYTES;
    const unsigned wl = wh + WS_BYTES;
    float* Vs = (float*)(smem_raw + 2 * XS_BYTES + 2 * WS_BYTES);

    const int tid = threadIdx.x;
    const int warp = tid >> 5;
    const int lane = tid & 31;
    const int g = lane >> 2;
    const int t = lane & 3;

    const int h = blockIdx.x & 255;
    const int b = blockIdx.x >> 8;
    const int cout0 = blockIdx.y << 6;

    Vs[tid] = g_valid[((b << 8) + h) * 256 + tid];

    // precomputed per-thread ldmatrix sub-addresses
    const unsigned a_lane = (lane & 15) * 32 + ((lane >> 4) << 4);
    const int b_lane = (lane & 7);
    const unsigned b_koff = (lane & 8) << 1;   // lanes 8-15 -> +16B (k8-15)

    float acc[4][4][4];
#pragma unroll
    for (int mf = 0; mf < 4; ++mf)
#pragma unroll
        for (int nf = 0; nf < 4; ++nf)
#pragma unroll
            for (int i = 0; i < 4; ++i) acc[mf][nf][i] = 0.0f;

    for (int cc = 0; cc < 12; ++cc) {
        __syncthreads();   // previous chunk's compute done before overwrite

        // --- stage weights: 9 taps x 64 m x 2 k-halves x 2 splits (cp.async 16B) ---
        for (int idx = tid; idx < 2304; idx += 256) {
            int s = idx & 1;
            int koff = (idx >> 1) & 1;
            int m = (idx >> 2) & 63;
            int tap = idx >> 8;
            const __nv_bfloat16* src =
                (s ? g_wlo : g_whi) + (tap * COUT + cout0 + m) * CIN + cc * 16 + koff * 8;
            unsigned dst = (s ? wl : wh) + sw(tap * 2048 + m * 32 + koff * 16);
            CP16(dst, src, 16);
        }
        // --- stage X halo: 3 rows x 258 pixels x 2 k-halves x 2 splits ---
        for (int idx = tid; idx < 3096; idx += 256) {
            int s = idx & 1;
            int koff = (idx >> 1) & 1;
            int rp = idx >> 2;
            int p = rp % 258;
            int rr = rp / 258;
            int hh = h - 1 + rr;
            int gw = p - 1;
            bool ok = ((unsigned)hh < 256u) && ((unsigned)gw < 256u);
            int hc = ok ? hh : 0;
            int wc = ok ? gw : 0;
            const __nv_bfloat16* src =
                (s ? g_xlo : g_xhi) + ((((b << 8) + hc) << 8) + wc) * CIN + cc * 16 + koff * 8;
            unsigned dst = (s ? xl : xh) + sw(rr * XROW + p * 32 + koff * 16);
            CP16(dst, src, ok ? 16 : 0);   // zero-fill padding
        }
        asm volatile("cp.async.commit_group;");
        asm volatile("cp.async.wait_group 0;" ::: "memory");
        __syncthreads();

        // --- compute: 9 taps x (Whi*Xhi + Whi*Xlo + Wlo*Xhi) via ldmatrix ---
#pragma unroll
        for (int tap = 0; tap < 9; ++tap) {
            const int kh = tap / 3;
            const int kw = tap - kh * 3;
            unsigned AH[4][4], AL[4][4];
#pragma unroll
            for (int mf = 0; mf < 4; ++mf) {
                unsigned aoff = sw((unsigned)(tap * 2048 + mf * 512) + a_lane);
                LDSM4(AH[mf], wh + aoff);
                LDSM4(AL[mf], wl + aoff);
            }
#pragma unroll
            for (int nf = 0; nf < 4; ++nf) {
                int sp = (warp << 5) + (nf << 3) + b_lane + kw;
                unsigned boff = sw((unsigned)(kh * XROW + sp * 32) + b_koff);
                unsigned b0, b1, c0, c1;
                LDSM2(b0, b1, xh + boff);
                LDSM2(c0, c1, xl + boff);
#pragma unroll
                for (int mf = 0; mf < 4; ++mf) {
                    mma_bf16(acc[mf][nf], AH[mf], b0, b1);
                    mma_bf16(acc[mf][nf], AH[mf], c0, c1);
                    mma_bf16(acc[mf][nf], AL[mf], b0, b1);
                }
            }
        }
    }

    // --- epilogue: +bias, * validity, store fp32 ---
#pragma unroll
    for (int mf = 0; mf < 4; ++mf) {
        int m0 = cout0 + mf * 16 + g;
        float bz0 = bias[m0];
        float bz1 = bias[m0 + 8];
#pragma unroll
        for (int nf = 0; nf < 4; ++nf) {
            int n = (warp << 5) + (nf << 3) + 2 * t;
            float v0 = Vs[n];
            float v1 = Vs[n + 1];
            int o = ((b * COUT + m0) * 256 + h) * 256 + n;
            float2 r0;
            r0.x = (acc[mf][nf][0] + bz0) * v0;
            r0.y = (acc[mf][nf][1] + bz0) * v1;
            *(float2*)(out + o) = r0;
            float2 r1;
            r1.x = (acc[mf][nf][2] + bz1) * v0;
            r1.y = (acc[mf][nf][3] + bz1) * v1;
            *(float2*)(out + o + 8 * 65536) = r1;
        }
    }
}

// ---------------------------------------------------------------------------
extern "C" void kernel_launch(void* const* d_in, const int* in_sizes, int n_in,
                              void* d_out, int out_size) {
    const float* x = (const float*)d_in[0];
    const int* mask = (const int*)d_in[1];
    const float* w = (const float*)d_in[2];
    const float* bias = (const float*)d_in[3];
    float* out = (float*)d_out;

    cudaFuncSetAttribute(conv_kernel, cudaFuncAttributeMaxDynamicSharedMemorySize,
                         SMEM_BYTES);

    dim3 tg(4, 256, NB);
    cvt_x_kernel<<<tg, 256>>>(x);
    cvt_w_kernel<<<(COUT * CIN * 9 + 255) / 256, 256>>>(w);
    valid_kernel<<<(NB * 256 * 256 + 255) / 256, 256>>>(mask);

    dim3 grid(NB * 256, 3, 1);
    conv_kernel<<<grid, 256, SMEM_BYTES>>>(bias, out);
}